// round 11
// baseline (speedup 1.0000x reference)
#include <cuda_runtime.h>
#include <cstdint>

#define BB   16
#define CC   32
#define HH   256
#define WW   256
#define T2   8
#define NT   16
#define NHC  32               // half-chunks (8 rows)
#define NQC  64               // quarter-chunks (4 rows each)
#define FIELD (HH*WW)
#define BT   (BB*T2)

typedef unsigned long long u64;

// ---------------- scratch (no cudaMalloc allowed) ----------------
__device__ __align__(256) float g_w1 [BT*FIELD];
__device__ __align__(256) float g_gv2[BT*FIELD];
__device__ __align__(256) float g_Sh [BT*3*NQC*WW];   // qc colsums (w3,w3p,w2p) -> suffix-excl after kS
__device__ __align__(256) float g_S3 [BT*NQC*WW];     // qc colsums of gv2 -> prefix-excl after kS2
__device__ u64 g_apk[T2*6*CC];                        // packed alphas

// ---------------- f32x2 helpers ----------------
__device__ __forceinline__ u64 fma2(u64 a, u64 b, u64 c) {
    u64 d; asm("fma.rn.f32x2 %0, %1, %2, %3;" : "=l"(d) : "l"(a), "l"(b), "l"(c)); return d;
}
__device__ __forceinline__ u64 add2(u64 a, u64 b) {
    u64 d; asm("add.rn.f32x2 %0, %1, %2;" : "=l"(d) : "l"(a), "l"(b)); return d;
}
__device__ __forceinline__ u64 pack2(float lo, float hi) {
    u64 r; asm("mov.b64 %0, {%1, %2};" : "=l"(r) : "f"(lo), "f"(hi)); return r;
}
__device__ __forceinline__ float2 unpack2(u64 v) {
    float2 f; asm("mov.b64 {%0, %1}, %2;" : "=f"(f.x), "=f"(f.y) : "l"(v)); return f;
}
__device__ __forceinline__ void LD8(float* v, const float* p) {
    float4 a = *(const float4*)p, b = *(const float4*)(p + 4);
    v[0]=a.x; v[1]=a.y; v[2]=a.z; v[3]=a.w; v[4]=b.x; v[5]=b.y; v[6]=b.z; v[7]=b.w;
}
__device__ __forceinline__ void ST8(float* p, const float* v) {
    *(float4*)p       = make_float4(v[0],v[1],v[2],v[3]);
    *(float4*)(p + 4) = make_float4(v[4],v[5],v[6],v[7]);
}

// ---------------- batched 64-lane scan (2 warps, 4 elems/lane) ----------------
template<int S>
__device__ __forceinline__ void scan_batch(float (*v)[4], float* exclLane, float* grand,
                                           float (*stot)[2], int lane, int wi)
{
    float wsum[S], wincl[S];
    #pragma unroll
    for (int s = 0; s < S; s++) {
        float r = v[s][0] + v[s][1] + v[s][2] + v[s][3];
        float xx = r;
        #pragma unroll
        for (int d = 1; d < 32; d <<= 1) {
            float n = __shfl_up_sync(0xffffffffu, xx, d);
            if (lane >= d) xx += n;
        }
        wsum[s] = r; wincl[s] = xx;
    }
    if (lane == 31) {
        #pragma unroll
        for (int s = 0; s < S; s++) stot[s][wi] = wincl[s];
    }
    __syncthreads();
    #pragma unroll
    for (int s = 0; s < S; s++) {
        float t0 = stot[s][0], t1 = stot[s][1];
        exclLane[s] = (wi ? t0 : 0.f) + (wincl[s] - wsum[s]);
        grand[s]    = t0 + t1;
    }
    __syncthreads();
}

// =====================================================================
// K0: pack alphas duplicated into f32x2 pairs
// field order: 0=a1 1=a2 2=a3 3=a1p 4=a2p 5=a3p
// =====================================================================
__global__ void k0_pack(const float* __restrict__ a1,  const float* __restrict__ a2,
                        const float* __restrict__ a3,  const float* __restrict__ a1p,
                        const float* __restrict__ a2p, const float* __restrict__ a3p)
{
    int i = blockIdx.x * 256 + threadIdx.x;          // T2*6*CC = 1536
    if (i >= T2 * 6 * CC) return;
    int c = i % CC, f = (i / CC) % 6, t = i / (6 * CC);
    const float* p = (f == 0) ? a1 : (f == 1) ? a2 : (f == 2) ? a3
                   : (f == 3) ? a1p : (f == 4) ? a2p : a3p;
    float v = p[t * CC + c];
    g_apk[(t * 6 + f) * CC + c] = pack2(v, v);
}

// =====================================================================
// KAB: raw quarterchunk colsums contracted with alphas (all 8 trees).
// CTA = halfchunk: 2 rowgroups x 64 lanes x float4. grid = (NHC, BB).
// =====================================================================
__global__ void __launch_bounds__(128) kAB_colsum(const float* __restrict__ x)
{
    __shared__ __align__(16) u64 s_alB[CC][24];   // slot = k*8 + t
    const int tid = threadIdx.x;
    const int rg  = tid >> 6;
    const int l   = tid & 63;
    const int hc  = blockIdx.x;
    const int b   = blockIdx.y;
    const int qc  = hc * 2 + rg;
    const int col = l * 4;

    for (int i = tid; i < CC * 24; i += 128) {
        int slot = i % 24, c = i / 24;
        int k = slot / 8, t = slot % 8;
        int f = (k == 0) ? 2 : (k == 1) ? 5 : 4;   // a3, a3p, a2p
        s_alB[c][slot] = g_apk[(t * 6 + f) * CC + c];
    }
    __syncthreads();

    u64 acc[24][2];
    #pragma unroll
    for (int s = 0; s < 24; s++) { acc[s][0] = 0ull; acc[s][1] = 0ull; }

    #pragma unroll 2
    for (int c = 0; c < CC; c++) {
        const float4* xp = (const float4*)(x
            + ((size_t)(b * CC + c) * HH + qc * 4) * WW + col);
        u64 s01 = 0ull, s23 = 0ull;
        #pragma unroll
        for (int r = 0; r < 4; r++) {
            float4 v = xp[r * (WW / 4)];
            s01 = add2(s01, pack2(v.x, v.y));
            s23 = add2(s23, pack2(v.z, v.w));
        }
        #pragma unroll
        for (int j = 0; j < 12; j++) {
            ulonglong2 p = *(const ulonglong2*)&s_alB[c][2 * j];
            acc[2*j][0]   = fma2(s01, p.x, acc[2*j][0]);
            acc[2*j][1]   = fma2(s23, p.x, acc[2*j][1]);
            acc[2*j+1][0] = fma2(s01, p.y, acc[2*j+1][0]);
            acc[2*j+1][1] = fma2(s23, p.y, acc[2*j+1][1]);
        }
    }

    #pragma unroll
    for (int k = 0; k < 3; k++)
        #pragma unroll
        for (int t = 0; t < T2; t++) {
            int s = k * 8 + t;
            float2 v0 = unpack2(acc[s][0]), v1 = unpack2(acc[s][1]);
            size_t o = (((size_t)(b * T2 + t) * 3 + k) * NQC + qc) * WW + col;
            *(float4*)&g_Sh[o] = make_float4(v0.x, v0.y, v1.x, v1.y);
        }
}

// =====================================================================
// KS: in-place exclusive SUFFIX sum of g_Sh along qc (per bt,k,w column)
// =====================================================================
__global__ void kS_suffix()
{
    int gid = blockIdx.x * 128 + threadIdx.x;   // BT*3*WW = 98304
    int w   = gid & (WW - 1);
    int ktb = gid >> 8;
    float* base = g_Sh + (size_t)ktb * NQC * WW + w;
    float v[NQC];
    #pragma unroll
    for (int j = 0; j < NQC; j++) v[j] = base[(size_t)j * WW];
    float s = 0.f;
    #pragma unroll
    for (int j = NQC - 1; j >= 0; j--) {
        base[(size_t)j * WW] = s;
        s += v[j];
    }
}

// =====================================================================
// KS2: in-place exclusive PREFIX sum of g_S3 along qc
// =====================================================================
__global__ void kS2_prefix()
{
    int gid = blockIdx.x * 128 + threadIdx.x;   // BT*WW = 32768
    int w   = gid & (WW - 1);
    int bt  = gid >> 8;
    float* base = g_S3 + (size_t)bt * NQC * WW + w;
    float v[NQC];
    #pragma unroll
    for (int j = 0; j < NQC; j++) v[j] = base[(size_t)j * WW];
    float s = 0.f;
    #pragma unroll
    for (int j = 0; j < NQC; j++) {
        base[(size_t)j * WW] = s;
        s += v[j];
    }
}

// =====================================================================
// K1_FUSED (R8 structure + deep prefetch): GEMM + bottom-up, CTA-level.
// CTA = (tree-pair, halfchunk, b). 128 thr = 2 rowgroups x 64 lanes x 4 cols.
// 4-deep ring prefetch on x; next row's first channels prefetched during
// the scan/store phase of the current row.
// Emits: cherry -> out, gv2, w1, S3 (raw qc colsums of gv2).
// =====================================================================
__global__ void __launch_bounds__(128) k1_fused(const float* __restrict__ x,
                                                float* __restrict__ out)
{
    __shared__ __align__(16) u64 s_al[2][CC][6];
    __shared__ float s_tot[2][8][2];

    const int tid  = threadIdx.x;
    const int rg   = tid >> 6;
    const int l    = tid & 63;
    const int lane = tid & 31;
    const int wi   = (tid >> 5) & 1;
    const int col  = l * 4;
    const int t0   = blockIdx.x * 2;
    const int hc   = blockIdx.y;
    const int b    = blockIdx.z;
    const int bt0  = b * T2 + t0;
    const int qc   = hc * 2 + rg;

    for (int i = tid; i < 2 * 6 * CC; i += 128) {
        int c = i % CC, f = (i / CC) % 6, tr = i / (6 * CC);
        s_al[tr][c][f] = g_apk[((t0 + tr) * 6 + f) * CC + c];
    }
    __syncthreads();

    // ---- init states from suffix-excl Sh tables ----
    float st[8][4];
    #pragma unroll
    for (int tr = 0; tr < 2; tr++)
        #pragma unroll
        for (int k = 0; k < 3; k++) {
            float4 v = *(const float4*)&g_Sh[
                (((size_t)(bt0 + tr) * 3 + k) * NQC + qc) * WW + col];
            st[tr*3+k][0]=v.x; st[tr*3+k][1]=v.y; st[tr*3+k][2]=v.z; st[tr*3+k][3]=v.w;
        }
    float ex[8], gr[8];
    scan_batch<6>(st, ex, gr, s_tot[rg], lane, wi);

    float a3[2][4], p3[2][4], p2[2][4], cs[2][4];
    #pragma unroll
    for (int tr = 0; tr < 2; tr++) {
        float run;
        run = 0.f;
        #pragma unroll
        for (int i = 0; i < 4; i++) { a3[tr][i] = ex[tr*3+0] + run; run += st[tr*3+0][i]; }
        run = 0.f;
        #pragma unroll
        for (int i = 0; i < 4; i++) { p3[tr][i] = ex[tr*3+1] + run; run += st[tr*3+1][i]; }
        run = 0.f;
        #pragma unroll
        for (int i = 0; i < 4; i++) { run += st[tr*3+2][i]; p2[tr][i] = gr[tr*3+2] - (ex[tr*3+2] + run); }
        #pragma unroll
        for (int i = 0; i < 4; i++) cs[tr][i] = 0.f;
    }

    const float* xbase = x + (size_t)b * CC * FIELD + col;

    // preload ring for first row (r=3)
    float4 ring[4];
    {
        const float4* xq = (const float4*)(xbase + (size_t)(qc * 4 + 3) * WW);
        #pragma unroll
        for (int j = 0; j < 4; j++) ring[j] = xq[(size_t)j * (FIELD / 4)];
    }

    // ---- 4 rows, bottom-up ----
    #pragma unroll 1
    for (int r = 3; r >= 0; r--) {
        const int h = qc * 4 + r;
        const float4* xq = (const float4*)(xbase + (size_t)h * WW);

        u64 acc[2][6][2];
        #pragma unroll
        for (int tr = 0; tr < 2; tr++)
            #pragma unroll
            for (int f = 0; f < 6; f++) { acc[tr][f][0] = 0ull; acc[tr][f][1] = 0ull; }

        #pragma unroll 4
        for (int c = 0; c < CC; c++) {
            float4 xv = ring[c & 3];
            if (c + 4 < CC)
                ring[c & 3] = xq[(size_t)(c + 4) * (FIELD / 4)];
            u64 x01 = pack2(xv.x, xv.y);
            u64 x23 = pack2(xv.z, xv.w);
            #pragma unroll
            for (int tr = 0; tr < 2; tr++) {
                ulonglong2 pA = *(const ulonglong2*)&s_al[tr][c][0];
                ulonglong2 pB = *(const ulonglong2*)&s_al[tr][c][2];
                ulonglong2 pC = *(const ulonglong2*)&s_al[tr][c][4];
                acc[tr][0][0] = fma2(x01, pA.x, acc[tr][0][0]);
                acc[tr][0][1] = fma2(x23, pA.x, acc[tr][0][1]);
                acc[tr][1][0] = fma2(x01, pA.y, acc[tr][1][0]);
                acc[tr][1][1] = fma2(x23, pA.y, acc[tr][1][1]);
                acc[tr][2][0] = fma2(x01, pB.x, acc[tr][2][0]);
                acc[tr][2][1] = fma2(x23, pB.x, acc[tr][2][1]);
                acc[tr][3][0] = fma2(x01, pB.y, acc[tr][3][0]);
                acc[tr][3][1] = fma2(x23, pB.y, acc[tr][3][1]);
                acc[tr][4][0] = fma2(x01, pC.x, acc[tr][4][0]);
                acc[tr][4][1] = fma2(x23, pC.x, acc[tr][4][1]);
                acc[tr][5][0] = fma2(x01, pC.y, acc[tr][5][0]);
                acc[tr][5][1] = fma2(x23, pC.y, acc[tr][5][1]);
            }
        }

        // prefetch next row's first channels while we do scans/stores
        if (r > 0) {
            const float4* xn = (const float4*)(xbase + (size_t)(h - 1) * WW);
            #pragma unroll
            for (int j = 0; j < 4; j++) ring[j] = xn[(size_t)j * (FIELD / 4)];
        }

        // stores needing only pre-update states: w1, cherry
        #pragma unroll
        for (int tr = 0; tr < 2; tr++) {
            const size_t ob = (size_t)(bt0 + tr) * FIELD + (size_t)h * WW + col;
            float2 w1a = unpack2(acc[tr][0][0]), w1b = unpack2(acc[tr][0][1]);
            *(float4*)&g_w1[ob] = make_float4(w1a.x, w1a.y, w1b.x, w1b.y);

            float2 pa = unpack2(acc[tr][3][0]), pb = unpack2(acc[tr][3][1]);
            float w1p[4] = {pa.x, pa.y, pb.x, pb.y};
            float ch[4];
            #pragma unroll
            for (int i = 0; i < 4; i++) ch[i] = w1p[i] * p3[tr][i] * p2[tr][i];
            *(float4*)&out[((size_t)(b * NT + T2 + t0 + tr)) * FIELD
                           + (size_t)h * WW + col] =
                make_float4(ch[0], ch[1], ch[2], ch[3]);
        }

        // batched scans: per tree {w3, w3p, w2p, v2}
        float sv[8][4];
        #pragma unroll
        for (int tr = 0; tr < 2; tr++) {
            float2 u0, u1;
            u0 = unpack2(acc[tr][2][0]); u1 = unpack2(acc[tr][2][1]);
            sv[tr*4+0][0]=u0.x; sv[tr*4+0][1]=u0.y; sv[tr*4+0][2]=u1.x; sv[tr*4+0][3]=u1.y;
            u0 = unpack2(acc[tr][5][0]); u1 = unpack2(acc[tr][5][1]);
            sv[tr*4+1][0]=u0.x; sv[tr*4+1][1]=u0.y; sv[tr*4+1][2]=u1.x; sv[tr*4+1][3]=u1.y;
            u0 = unpack2(acc[tr][4][0]); u1 = unpack2(acc[tr][4][1]);
            sv[tr*4+2][0]=u0.x; sv[tr*4+2][1]=u0.y; sv[tr*4+2][2]=u1.x; sv[tr*4+2][3]=u1.y;
            u0 = unpack2(acc[tr][1][0]); u1 = unpack2(acc[tr][1][1]);
            float w2v[4] = {u0.x, u0.y, u1.x, u1.y};
            #pragma unroll
            for (int i = 0; i < 4; i++) sv[tr*4+3][i] = w2v[i] * a3[tr][i];
        }
        scan_batch<8>(sv, ex, gr, s_tot[rg], lane, wi);

        #pragma unroll
        for (int tr = 0; tr < 2; tr++) {
            const size_t ob = (size_t)(bt0 + tr) * FIELD + (size_t)h * WW + col;
            float run, gv[4];
            run = 0.f;
            #pragma unroll
            for (int i = 0; i < 4; i++) {
                run += sv[tr*4+3][i];
                gv[i] = gr[tr*4+3] - (ex[tr*4+3] + run);
                cs[tr][i] += gv[i];
            }
            *(float4*)&g_gv2[ob] = make_float4(gv[0], gv[1], gv[2], gv[3]);
            run = 0.f;
            #pragma unroll
            for (int i = 0; i < 4; i++) { a3[tr][i] += ex[tr*4+0] + run; run += sv[tr*4+0][i]; }
            run = 0.f;
            #pragma unroll
            for (int i = 0; i < 4; i++) { p3[tr][i] += ex[tr*4+1] + run; run += sv[tr*4+1][i]; }
            run = 0.f;
            #pragma unroll
            for (int i = 0; i < 4; i++) { run += sv[tr*4+2][i]; p2[tr][i] += gr[tr*4+2] - (ex[tr*4+2] + run); }
        }
    }

    #pragma unroll
    for (int tr = 0; tr < 2; tr++) {
        size_t o = ((size_t)(bt0 + tr) * NQC + qc) * WW + col;
        *(float4*)&g_S3[o] = make_float4(cs[tr][0], cs[tr][1], cs[tr][2], cs[tr][3]);
    }
}

// =====================================================================
// KD: top-down. linear = w1 * strict-north colsum of gv2.
// One warp per (qc,t,b) = 8192 warps; init from prefix-excl S3.
// =====================================================================
__global__ void __launch_bounds__(128) kD_topdown(float* __restrict__ out)
{
    const int wid  = threadIdx.x >> 5;
    const int lane = threadIdx.x & 31;
    const int gw   = blockIdx.x * 4 + wid;
    const int qc   =  gw        & 63;
    const int t    = (gw >> 6)  & 7;
    const int b    =  gw >> 9;
    const int bt   = b * T2 + t;
    const int col  = lane * 8;

    float va[8];
    LD8(va, g_S3 + ((size_t)bt * NQC + qc) * WW + col);   // prefix-excl

    const size_t fbase = (size_t)bt * FIELD + (size_t)(qc * 4) * WW + col;
    const size_t obase = ((size_t)(b * NT + t)) * FIELD + (size_t)(qc * 4) * WW + col;

    float w1b[8], gvb[8];
    LD8(w1b, g_w1 + fbase);
    LD8(gvb, g_gv2 + fbase);

    #pragma unroll
    for (int r = 0; r < 4; r++) {
        float w1n[8], gvn[8];
        if (r < 3) {
            LD8(w1n, g_w1  + fbase + (size_t)(r + 1) * WW);
            LD8(gvn, g_gv2 + fbase + (size_t)(r + 1) * WW);
        }
        float o[8];
        #pragma unroll
        for (int i = 0; i < 8; i++) o[i] = w1b[i] * va[i];
        ST8(out + obase + (size_t)r * WW, o);
        #pragma unroll
        for (int i = 0; i < 8; i++) va[i] += gvb[i];
        if (r < 3) {
            #pragma unroll
            for (int i = 0; i < 8; i++) { w1b[i] = w1n[i]; gvb[i] = gvn[i]; }
        }
    }
}

// =====================================================================
extern "C" void kernel_launch(void* const* d_in, const int* in_sizes, int n_in,
                              void* d_out, int out_size)
{
    const float* x   = (const float*)d_in[0];
    const float* a1  = (const float*)d_in[1];
    const float* a2  = (const float*)d_in[2];
    const float* a3  = (const float*)d_in[3];
    const float* a1p = (const float*)d_in[4];
    const float* a2p = (const float*)d_in[5];
    const float* a3p = (const float*)d_in[6];
    float* out = (float*)d_out;

    k0_pack<<<6, 256>>>(a1, a2, a3, a1p, a2p, a3p);

    dim3 gAB(NHC, BB);                          // (32, 16)
    kAB_colsum<<<gAB, 128>>>(x);

    kS_suffix<<<BT * 3 * WW / 128, 128>>>();    // 768 blocks

    dim3 gC(T2 / 2, HH / 8, BB);                // (4, 32, 16) = 2048 CTAs
    k1_fused<<<gC, 128>>>(x, out);

    kS2_prefix<<<BT * WW / 128, 128>>>();       // 256 blocks

    kD_topdown<<<BT * NQC / 4, 128>>>(out);     // 2048 blocks
}

// round 12
// speedup vs baseline: 1.0534x; 1.0534x over previous
#include <cuda_runtime.h>
#include <cstdint>

#define BB   16
#define CC   32
#define HH   256
#define WW   256
#define T2   8
#define NT   16
#define NHC  32               // half-chunks (8 rows)
#define NQC  64               // quarter-chunks (4 rows each)
#define FIELD (HH*WW)
#define BT   (BB*T2)

typedef unsigned long long u64;

// ---------------- scratch (no cudaMalloc allowed) ----------------
__device__ __align__(256) float g_w1 [BT*FIELD];
__device__ __align__(256) float g_gv2[BT*FIELD];
__device__ __align__(256) float g_Sh [BT*3*NQC*WW];   // qc colsums (w3,w3p,w2p) -> suffix-excl after kS
__device__ __align__(256) float g_S3 [BT*NQC*WW];     // qc colsums of gv2 -> prefix-excl after kS2
__device__ u64 g_apk[T2*6*CC];                        // packed alphas

// ---------------- f32x2 helpers ----------------
__device__ __forceinline__ u64 fma2(u64 a, u64 b, u64 c) {
    u64 d; asm("fma.rn.f32x2 %0, %1, %2, %3;" : "=l"(d) : "l"(a), "l"(b), "l"(c)); return d;
}
__device__ __forceinline__ u64 add2(u64 a, u64 b) {
    u64 d; asm("add.rn.f32x2 %0, %1, %2;" : "=l"(d) : "l"(a), "l"(b)); return d;
}
__device__ __forceinline__ u64 pack2(float lo, float hi) {
    u64 r; asm("mov.b64 %0, {%1, %2};" : "=l"(r) : "f"(lo), "f"(hi)); return r;
}
__device__ __forceinline__ float2 unpack2(u64 v) {
    float2 f; asm("mov.b64 {%0, %1}, %2;" : "=f"(f.x), "=f"(f.y) : "l"(v)); return f;
}
__device__ __forceinline__ void LD8(float* v, const float* p) {
    float4 a = *(const float4*)p, b = *(const float4*)(p + 4);
    v[0]=a.x; v[1]=a.y; v[2]=a.z; v[3]=a.w; v[4]=b.x; v[5]=b.y; v[6]=b.z; v[7]=b.w;
}
__device__ __forceinline__ void ST8(float* p, const float* v) {
    *(float4*)p       = make_float4(v[0],v[1],v[2],v[3]);
    *(float4*)(p + 4) = make_float4(v[4],v[5],v[6],v[7]);
}

// ---------------- batched 64-lane scan (2 warps, 4 elems/lane) ----------------
template<int S>
__device__ __forceinline__ void scan_batch(float (*v)[4], float* exclLane, float* grand,
                                           float (*stot)[2], int lane, int wi)
{
    float wsum[S], wincl[S];
    #pragma unroll
    for (int s = 0; s < S; s++) {
        float r = v[s][0] + v[s][1] + v[s][2] + v[s][3];
        float xx = r;
        #pragma unroll
        for (int d = 1; d < 32; d <<= 1) {
            float n = __shfl_up_sync(0xffffffffu, xx, d);
            if (lane >= d) xx += n;
        }
        wsum[s] = r; wincl[s] = xx;
    }
    if (lane == 31) {
        #pragma unroll
        for (int s = 0; s < S; s++) stot[s][wi] = wincl[s];
    }
    __syncthreads();
    #pragma unroll
    for (int s = 0; s < S; s++) {
        float t0 = stot[s][0], t1 = stot[s][1];
        exclLane[s] = (wi ? t0 : 0.f) + (wincl[s] - wsum[s]);
        grand[s]    = t0 + t1;
    }
    __syncthreads();
}

// =====================================================================
// K0: pack alphas duplicated into f32x2 pairs
// field order: 0=a1 1=a2 2=a3 3=a1p 4=a2p 5=a3p
// =====================================================================
__global__ void k0_pack(const float* __restrict__ a1,  const float* __restrict__ a2,
                        const float* __restrict__ a3,  const float* __restrict__ a1p,
                        const float* __restrict__ a2p, const float* __restrict__ a3p)
{
    int i = blockIdx.x * 256 + threadIdx.x;          // T2*6*CC = 1536
    if (i >= T2 * 6 * CC) return;
    int c = i % CC, f = (i / CC) % 6, t = i / (6 * CC);
    const float* p = (f == 0) ? a1 : (f == 1) ? a2 : (f == 2) ? a3
                   : (f == 3) ? a1p : (f == 4) ? a2p : a3p;
    float v = p[t * CC + c];
    g_apk[(t * 6 + f) * CC + c] = pack2(v, v);
}

// =====================================================================
// KAB: raw quarterchunk colsums contracted with alphas (all 8 trees).
// CTA = halfchunk: 2 rowgroups x 64 lanes x float4. grid = (NHC, BB).
// =====================================================================
__global__ void __launch_bounds__(128) kAB_colsum(const float* __restrict__ x)
{
    __shared__ __align__(16) u64 s_alB[CC][24];   // slot = k*8 + t
    const int tid = threadIdx.x;
    const int rg  = tid >> 6;
    const int l   = tid & 63;
    const int hc  = blockIdx.x;
    const int b   = blockIdx.y;
    const int qc  = hc * 2 + rg;
    const int col = l * 4;

    for (int i = tid; i < CC * 24; i += 128) {
        int slot = i % 24, c = i / 24;
        int k = slot / 8, t = slot % 8;
        int f = (k == 0) ? 2 : (k == 1) ? 5 : 4;   // a3, a3p, a2p
        s_alB[c][slot] = g_apk[(t * 6 + f) * CC + c];
    }
    __syncthreads();

    u64 acc[24][2];
    #pragma unroll
    for (int s = 0; s < 24; s++) { acc[s][0] = 0ull; acc[s][1] = 0ull; }

    #pragma unroll 2
    for (int c = 0; c < CC; c++) {
        const float4* xp = (const float4*)(x
            + ((size_t)(b * CC + c) * HH + qc * 4) * WW + col);
        u64 s01 = 0ull, s23 = 0ull;
        #pragma unroll
        for (int r = 0; r < 4; r++) {
            float4 v = xp[r * (WW / 4)];
            s01 = add2(s01, pack2(v.x, v.y));
            s23 = add2(s23, pack2(v.z, v.w));
        }
        #pragma unroll
        for (int j = 0; j < 12; j++) {
            ulonglong2 p = *(const ulonglong2*)&s_alB[c][2 * j];
            acc[2*j][0]   = fma2(s01, p.x, acc[2*j][0]);
            acc[2*j][1]   = fma2(s23, p.x, acc[2*j][1]);
            acc[2*j+1][0] = fma2(s01, p.y, acc[2*j+1][0]);
            acc[2*j+1][1] = fma2(s23, p.y, acc[2*j+1][1]);
        }
    }

    #pragma unroll
    for (int k = 0; k < 3; k++)
        #pragma unroll
        for (int t = 0; t < T2; t++) {
            int s = k * 8 + t;
            float2 v0 = unpack2(acc[s][0]), v1 = unpack2(acc[s][1]);
            size_t o = (((size_t)(b * T2 + t) * 3 + k) * NQC + qc) * WW + col;
            *(float4*)&g_Sh[o] = make_float4(v0.x, v0.y, v1.x, v1.y);
        }
}

// =====================================================================
// KS: in-place exclusive SUFFIX sum of g_Sh along qc (per bt,k,w column)
// =====================================================================
__global__ void kS_suffix()
{
    int gid = blockIdx.x * 128 + threadIdx.x;   // BT*3*WW = 98304
    int w   = gid & (WW - 1);
    int ktb = gid >> 8;
    float* base = g_Sh + (size_t)ktb * NQC * WW + w;
    float v[NQC];
    #pragma unroll
    for (int j = 0; j < NQC; j++) v[j] = base[(size_t)j * WW];
    float s = 0.f;
    #pragma unroll
    for (int j = NQC - 1; j >= 0; j--) {
        base[(size_t)j * WW] = s;
        s += v[j];
    }
}

// =====================================================================
// KS2: in-place exclusive PREFIX sum of g_S3 along qc
// =====================================================================
__global__ void kS2_prefix()
{
    int gid = blockIdx.x * 128 + threadIdx.x;   // BT*WW = 32768
    int w   = gid & (WW - 1);
    int bt  = gid >> 8;
    float* base = g_S3 + (size_t)bt * NQC * WW + w;
    float v[NQC];
    #pragma unroll
    for (int j = 0; j < NQC; j++) v[j] = base[(size_t)j * WW];
    float s = 0.f;
    #pragma unroll
    for (int j = 0; j < NQC; j++) {
        base[(size_t)j * WW] = s;
        s += v[j];
    }
}

// =====================================================================
// K1_FUSED v3: ONE TREE per CTA (register diet -> occupancy).
// CTA = (tree, halfchunk, b). 128 thr = 2 rowgroups x 64 lanes x 4 cols.
// Per channel: 12 FFMA2 + 3 LDS.128 + 1 LDG.128. ~80 regs, 6 CTAs/SM.
// Emits: cherry -> out, gv2, w1, S3 (raw qc colsums of gv2).
// grid = (T2, NHC, BB) = 4096 CTAs.
// =====================================================================
__global__ void __launch_bounds__(128, 6) k1_fused(const float* __restrict__ x,
                                                   float* __restrict__ out)
{
    __shared__ __align__(16) u64 s_al[CC][6];
    __shared__ float s_tot[2][4][2];

    const int tid  = threadIdx.x;
    const int rg   = tid >> 6;
    const int l    = tid & 63;
    const int lane = tid & 31;
    const int wi   = (tid >> 5) & 1;
    const int col  = l * 4;
    const int t    = blockIdx.x;
    const int hc   = blockIdx.y;
    const int b    = blockIdx.z;
    const int bt   = b * T2 + t;
    const int qc   = hc * 2 + rg;

    for (int i = tid; i < 6 * CC; i += 128) {
        int f = i % 6, c = i / 6;
        s_al[c][f] = g_apk[(t * 6 + f) * CC + c];
    }
    __syncthreads();

    // ---- init states from suffix-excl Sh tables ----
    float st[3][4];
    #pragma unroll
    for (int k = 0; k < 3; k++) {
        float4 v = *(const float4*)&g_Sh[
            (((size_t)bt * 3 + k) * NQC + qc) * WW + col];
        st[k][0]=v.x; st[k][1]=v.y; st[k][2]=v.z; st[k][3]=v.w;
    }
    float ex[4], gr[4];
    scan_batch<3>(st, ex, gr, s_tot[rg], lane, wi);

    float a3[4], p3[4], p2[4], cs[4];
    {
        float run;
        run = 0.f;
        #pragma unroll
        for (int i = 0; i < 4; i++) { a3[i] = ex[0] + run; run += st[0][i]; }
        run = 0.f;
        #pragma unroll
        for (int i = 0; i < 4; i++) { p3[i] = ex[1] + run; run += st[1][i]; }
        run = 0.f;
        #pragma unroll
        for (int i = 0; i < 4; i++) { run += st[2][i]; p2[i] = gr[2] - (ex[2] + run); }
        #pragma unroll
        for (int i = 0; i < 4; i++) cs[i] = 0.f;
    }

    // ---- 4 rows, bottom-up ----
    #pragma unroll 1
    for (int r = 3; r >= 0; r--) {
        const int h = qc * 4 + r;

        u64 acc[6][2];
        #pragma unroll
        for (int f = 0; f < 6; f++) { acc[f][0] = 0ull; acc[f][1] = 0ull; }

        const float4* xq = (const float4*)(x + (size_t)b * CC * FIELD
                                             + (size_t)h * WW + col);
        float4 xb = xq[0];
        #pragma unroll 8
        for (int c = 0; c < CC; c++) {
            float4 nx;
            if (c < CC - 1) nx = xq[(size_t)(c + 1) * (FIELD / 4)];
            u64 x01 = pack2(xb.x, xb.y);
            u64 x23 = pack2(xb.z, xb.w);
            ulonglong2 pA = *(const ulonglong2*)&s_al[c][0];
            ulonglong2 pB = *(const ulonglong2*)&s_al[c][2];
            ulonglong2 pC = *(const ulonglong2*)&s_al[c][4];
            acc[0][0] = fma2(x01, pA.x, acc[0][0]);
            acc[0][1] = fma2(x23, pA.x, acc[0][1]);
            acc[1][0] = fma2(x01, pA.y, acc[1][0]);
            acc[1][1] = fma2(x23, pA.y, acc[1][1]);
            acc[2][0] = fma2(x01, pB.x, acc[2][0]);
            acc[2][1] = fma2(x23, pB.x, acc[2][1]);
            acc[3][0] = fma2(x01, pB.y, acc[3][0]);
            acc[3][1] = fma2(x23, pB.y, acc[3][1]);
            acc[4][0] = fma2(x01, pC.x, acc[4][0]);
            acc[4][1] = fma2(x23, pC.x, acc[4][1]);
            acc[5][0] = fma2(x01, pC.y, acc[5][0]);
            acc[5][1] = fma2(x23, pC.y, acc[5][1]);
            if (c < CC - 1) xb = nx;
        }

        // stores needing only pre-update states: w1, cherry
        {
            const size_t ob = (size_t)bt * FIELD + (size_t)h * WW + col;
            float2 w1a = unpack2(acc[0][0]), w1b = unpack2(acc[0][1]);
            *(float4*)&g_w1[ob] = make_float4(w1a.x, w1a.y, w1b.x, w1b.y);

            float2 pa = unpack2(acc[3][0]), pb = unpack2(acc[3][1]);
            float w1p[4] = {pa.x, pa.y, pb.x, pb.y};
            float ch[4];
            #pragma unroll
            for (int i = 0; i < 4; i++) ch[i] = w1p[i] * p3[i] * p2[i];
            *(float4*)&out[((size_t)(b * NT + T2 + t)) * FIELD
                           + (size_t)h * WW + col] =
                make_float4(ch[0], ch[1], ch[2], ch[3]);
        }

        // batched scans: {w3, w3p, w2p, v2}
        float sv[4][4];
        {
            float2 u0, u1;
            u0 = unpack2(acc[2][0]); u1 = unpack2(acc[2][1]);
            sv[0][0]=u0.x; sv[0][1]=u0.y; sv[0][2]=u1.x; sv[0][3]=u1.y;
            u0 = unpack2(acc[5][0]); u1 = unpack2(acc[5][1]);
            sv[1][0]=u0.x; sv[1][1]=u0.y; sv[1][2]=u1.x; sv[1][3]=u1.y;
            u0 = unpack2(acc[4][0]); u1 = unpack2(acc[4][1]);
            sv[2][0]=u0.x; sv[2][1]=u0.y; sv[2][2]=u1.x; sv[2][3]=u1.y;
            u0 = unpack2(acc[1][0]); u1 = unpack2(acc[1][1]);
            float w2v[4] = {u0.x, u0.y, u1.x, u1.y};
            #pragma unroll
            for (int i = 0; i < 4; i++) sv[3][i] = w2v[i] * a3[i];
        }
        scan_batch<4>(sv, ex, gr, s_tot[rg], lane, wi);

        {
            const size_t ob = (size_t)bt * FIELD + (size_t)h * WW + col;
            float run, gv[4];
            run = 0.f;
            #pragma unroll
            for (int i = 0; i < 4; i++) {
                run += sv[3][i];
                gv[i] = gr[3] - (ex[3] + run);
                cs[i] += gv[i];
            }
            *(float4*)&g_gv2[ob] = make_float4(gv[0], gv[1], gv[2], gv[3]);
            run = 0.f;
            #pragma unroll
            for (int i = 0; i < 4; i++) { a3[i] += ex[0] + run; run += sv[0][i]; }
            run = 0.f;
            #pragma unroll
            for (int i = 0; i < 4; i++) { p3[i] += ex[1] + run; run += sv[1][i]; }
            run = 0.f;
            #pragma unroll
            for (int i = 0; i < 4; i++) { run += sv[2][i]; p2[i] += gr[2] - (ex[2] + run); }
        }
    }

    {
        size_t o = ((size_t)bt * NQC + qc) * WW + col;
        *(float4*)&g_S3[o] = make_float4(cs[0], cs[1], cs[2], cs[3]);
    }
}

// =====================================================================
// KD: top-down. linear = w1 * strict-north colsum of gv2.
// One warp per (qc,t,b) = 8192 warps; init from prefix-excl S3.
// =====================================================================
__global__ void __launch_bounds__(128) kD_topdown(float* __restrict__ out)
{
    const int wid  = threadIdx.x >> 5;
    const int lane = threadIdx.x & 31;
    const int gw   = blockIdx.x * 4 + wid;
    const int qc   =  gw        & 63;
    const int t    = (gw >> 6)  & 7;
    const int b    =  gw >> 9;
    const int bt   = b * T2 + t;
    const int col  = lane * 8;

    float va[8];
    LD8(va, g_S3 + ((size_t)bt * NQC + qc) * WW + col);   // prefix-excl

    const size_t fbase = (size_t)bt * FIELD + (size_t)(qc * 4) * WW + col;
    const size_t obase = ((size_t)(b * NT + t)) * FIELD + (size_t)(qc * 4) * WW + col;

    float w1b[8], gvb[8];
    LD8(w1b, g_w1 + fbase);
    LD8(gvb, g_gv2 + fbase);

    #pragma unroll
    for (int r = 0; r < 4; r++) {
        float w1n[8], gvn[8];
        if (r < 3) {
            LD8(w1n, g_w1  + fbase + (size_t)(r + 1) * WW);
            LD8(gvn, g_gv2 + fbase + (size_t)(r + 1) * WW);
        }
        float o[8];
        #pragma unroll
        for (int i = 0; i < 8; i++) o[i] = w1b[i] * va[i];
        ST8(out + obase + (size_t)r * WW, o);
        #pragma unroll
        for (int i = 0; i < 8; i++) va[i] += gvb[i];
        if (r < 3) {
            #pragma unroll
            for (int i = 0; i < 8; i++) { w1b[i] = w1n[i]; gvb[i] = gvn[i]; }
        }
    }
}

// =====================================================================
extern "C" void kernel_launch(void* const* d_in, const int* in_sizes, int n_in,
                              void* d_out, int out_size)
{
    const float* x   = (const float*)d_in[0];
    const float* a1  = (const float*)d_in[1];
    const float* a2  = (const float*)d_in[2];
    const float* a3  = (const float*)d_in[3];
    const float* a1p = (const float*)d_in[4];
    const float* a2p = (const float*)d_in[5];
    const float* a3p = (const float*)d_in[6];
    float* out = (float*)d_out;

    k0_pack<<<6, 256>>>(a1, a2, a3, a1p, a2p, a3p);

    dim3 gAB(NHC, BB);                          // (32, 16)
    kAB_colsum<<<gAB, 128>>>(x);

    kS_suffix<<<BT * 3 * WW / 128, 128>>>();    // 768 blocks

    dim3 gC(T2, NHC, BB);                       // (8, 32, 16) = 4096 CTAs
    k1_fused<<<gC, 128>>>(x, out);

    kS2_prefix<<<BT * WW / 128, 128>>>();       // 256 blocks

    kD_topdown<<<BT * NQC / 4, 128>>>(out);     // 2048 blocks
}